// round 5
// baseline (speedup 1.0000x reference)
#include <cuda_runtime.h>

// Shapes fixed by the problem: N=8192, D=64.
#define N_ROWS 8192
#define D_DIM  64

#define COLS4          (N_ROWS / 4)      // 2048 float4 per row
#define THREADS        256
#define STRIP4         512               // float4s per strip (2048 floats, 8KB)
#define STRIPS         (COLS4 / STRIP4)  // 4 strips
#define ROWS_PER_BLOCK 32

// Scratch for GEMV results (no cudaMalloc allowed).
__device__ float g_s1[N_ROWS];
__device__ float g_s2[N_ROWS];

// Kernel 1: s1 = Wh @ a[:64], s2 = Wh @ a[64:128].
// One warp per row; each lane owns a float2 (64 elems / 32 lanes).
__global__ void gemv_kernel(const float* __restrict__ Wh,
                            const float* __restrict__ a) {
    const int warps_per_block = blockDim.x >> 5;
    const int row  = blockIdx.x * warps_per_block + (threadIdx.x >> 5);
    const int lane = threadIdx.x & 31;
    if (row >= N_ROWS) return;

    const float2 w  = reinterpret_cast<const float2*>(Wh + (size_t)row * D_DIM)[lane];
    const float2 a1 = reinterpret_cast<const float2*>(a)[lane];
    const float2 a2 = reinterpret_cast<const float2*>(a + D_DIM)[lane];

    float s1 = w.x * a1.x + w.y * a1.y;
    float s2 = w.x * a2.x + w.y * a2.y;

    #pragma unroll
    for (int off = 16; off > 0; off >>= 1) {
        s1 += __shfl_xor_sync(0xFFFFFFFFu, s1, off);
        s2 += __shfl_xor_sync(0xFFFFFFFFu, s2, off);
    }
    if (lane == 0) {
        g_s1[row] = s1;
        g_s2[row] = s2;
    }
}

__device__ __forceinline__ float leaky(float e) {
    // e >= 0 ? e : 0.2*e  ==  max(e, 0.2*e) for all e
    return fmaxf(e, 0.2f * e);
}

__device__ __forceinline__ float4 row_vals(float s1, float4 s2) {
    float4 e;
    e.x = leaky(s1 + s2.x);
    e.y = leaky(s1 + s2.y);
    e.z = leaky(s1 + s2.z);
    e.w = leaky(s1 + s2.w);
    return e;
}

// Kernel 2: out[i][j] = leaky(s1[i] + s2[j]).
// Each block owns a 2048-float (8KB) column strip; each thread holds TWO
// adjacent s2 float4s in registers and writes 32B contiguous per row.
// Loop over 32 rows, unrolled x2 -> 4 independent stores in flight.
__global__ __launch_bounds__(THREADS) void outer_kernel(float4* __restrict__ out) {
    const int t    = threadIdx.x;
    const int c4   = blockIdx.x * STRIP4 + t * 2;          // this thread's first float4
    const int row0 = blockIdx.y * ROWS_PER_BLOCK;

    const float4 s2a = reinterpret_cast<const float4*>(g_s2)[c4 + 0];
    const float4 s2b = reinterpret_cast<const float4*>(g_s2)[c4 + 1];

    float4* dst = out + (size_t)row0 * COLS4 + c4;

    #pragma unroll 4
    for (int r = 0; r < ROWS_PER_BLOCK; r += 2) {
        float v0 = g_s1[row0 + r + 0];
        float v1 = g_s1[row0 + r + 1];

        __stcs(dst + 0,                     row_vals(v0, s2a));
        __stcs(dst + 1,                     row_vals(v0, s2b));
        __stcs(dst + (size_t)COLS4 + 0,     row_vals(v1, s2a));
        __stcs(dst + (size_t)COLS4 + 1,     row_vals(v1, s2b));
        dst += 2 * (size_t)COLS4;
    }
}

extern "C" void kernel_launch(void* const* d_in, const int* in_sizes, int n_in,
                              void* d_out, int out_size) {
    const float* Wh = (const float*)d_in[0];
    const float* a  = (const float*)d_in[1];
    float4* out = (float4*)d_out;

    // Kernel 1: 8192 warps -> 8 warps/block, 1024 blocks
    gemv_kernel<<<N_ROWS / 8, 256>>>(Wh, a);

    // Kernel 2: 4 strips x 256 row-chunks = 1024 blocks
    dim3 grid(STRIPS, N_ROWS / ROWS_PER_BLOCK);
    outer_kernel<<<grid, THREADS>>>(out);
}

// round 6
// speedup vs baseline: 1.7646x; 1.7646x over previous
#include <cuda_runtime.h>

// Shapes fixed by the problem: N=8192, D=64.
#define N_ROWS 8192
#define D_DIM  64

#define COLS4          (N_ROWS / 4)      // 2048 float4 per row
#define THREADS        256
#define STRIP4         512               // float4s per strip (2048 floats, 8KB/row)
#define STRIPS         (COLS4 / STRIP4)  // 4 strips
#define ROWS_PER_BLOCK 32

// Scratch for GEMV results (no cudaMalloc allowed).
__device__ float g_s1[N_ROWS];
__device__ float g_s2[N_ROWS];

// Kernel 1: s1 = Wh @ a[:64], s2 = Wh @ a[64:128].
// One warp per row; each lane owns a float2 (64 elems / 32 lanes).
__global__ void gemv_kernel(const float* __restrict__ Wh,
                            const float* __restrict__ a) {
    const int warps_per_block = blockDim.x >> 5;
    const int row  = blockIdx.x * warps_per_block + (threadIdx.x >> 5);
    const int lane = threadIdx.x & 31;
    if (row >= N_ROWS) return;

    const float2 w  = reinterpret_cast<const float2*>(Wh + (size_t)row * D_DIM)[lane];
    const float2 a1 = reinterpret_cast<const float2*>(a)[lane];
    const float2 a2 = reinterpret_cast<const float2*>(a + D_DIM)[lane];

    float s1 = w.x * a1.x + w.y * a1.y;
    float s2 = w.x * a2.x + w.y * a2.y;

    #pragma unroll
    for (int off = 16; off > 0; off >>= 1) {
        s1 += __shfl_xor_sync(0xFFFFFFFFu, s1, off);
        s2 += __shfl_xor_sync(0xFFFFFFFFu, s2, off);
    }
    if (lane == 0) {
        g_s1[row] = s1;
        g_s2[row] = s2;
    }
}

__device__ __forceinline__ float leaky(float e) {
    // e >= 0 ? e : 0.2*e  ==  max(e, 0.2*e) for all e
    return fmaxf(e, 0.2f * e);
}

__device__ __forceinline__ float4 row_vals(float s1, float4 s2) {
    float4 e;
    e.x = leaky(s1 + s2.x);
    e.y = leaky(s1 + s2.y);
    e.z = leaky(s1 + s2.z);
    e.w = leaky(s1 + s2.w);
    return e;
}

// Kernel 2: out[i][j] = leaky(s1[i] + s2[j]).
// Each block owns a 2048-float (8KB per row) column strip. Thread t owns
// float4 columns t and t+256 -> both STGs are warp-contiguous (lanes
// adjacent, 512B per warp per instruction). Two coalesced 4KB segments
// per row. Loop over 32 rows, unrolled x2 -> 4 independent stores in flight.
__global__ __launch_bounds__(THREADS) void outer_kernel(float4* __restrict__ out) {
    const int t    = threadIdx.x;
    const int c4   = blockIdx.x * STRIP4 + t;   // first float4 column
    const int row0 = blockIdx.y * ROWS_PER_BLOCK;

    const float4 s2a = reinterpret_cast<const float4*>(g_s2)[c4];
    const float4 s2b = reinterpret_cast<const float4*>(g_s2)[c4 + THREADS];

    float4* dst = out + (size_t)row0 * COLS4 + c4;

    #pragma unroll 4
    for (int r = 0; r < ROWS_PER_BLOCK; r += 2) {
        float v0 = g_s1[row0 + r + 0];
        float v1 = g_s1[row0 + r + 1];

        __stcs(dst + 0,                       row_vals(v0, s2a));
        __stcs(dst + THREADS,                 row_vals(v0, s2b));
        __stcs(dst + (size_t)COLS4,           row_vals(v1, s2a));
        __stcs(dst + (size_t)COLS4 + THREADS, row_vals(v1, s2b));
        dst += 2 * (size_t)COLS4;
    }
}

extern "C" void kernel_launch(void* const* d_in, const int* in_sizes, int n_in,
                              void* d_out, int out_size) {
    const float* Wh = (const float*)d_in[0];
    const float* a  = (const float*)d_in[1];
    float4* out = (float4*)d_out;

    // Kernel 1: 8192 warps -> 8 warps/block, 1024 blocks
    gemv_kernel<<<N_ROWS / 8, 256>>>(Wh, a);

    // Kernel 2: 4 strips x 256 row-chunks = 1024 blocks
    dim3 grid(STRIPS, N_ROWS / ROWS_PER_BLOCK);
    outer_kernel<<<grid, THREADS>>>(out);
}